// round 1
// baseline (speedup 1.0000x reference)
#include <cuda_runtime.h>
#include <cstdint>

#define MAXN 100000
#define DIM 128

// ---------------- device scratch (no allocations allowed) ----------------
__device__ float g_all[(size_t)MAXN * 512];        // [N][512] concat embeddings
__device__ float g_ego[2][(size_t)MAXN * DIM];     // ping-pong ego buffers
__device__ float g_msg[(size_t)MAXN * DIM];        // segment-sum accumulator
__device__ float g_wcat[3 * 256 * 128];            // [layer][k][j] combined W (transposed)
__device__ float g_bias[3 * 128];                  // gc_b + bi_b

// ---------------- prep: transpose/combine weights ----------------
__global__ void prep_kernel(const float* __restrict__ gcw, const float* __restrict__ gcb,
                            const float* __restrict__ biw, const float* __restrict__ bib) {
    int t = blockIdx.x * blockDim.x + threadIdx.x;
    if (t >= 3 * 256 * 128) return;
    int i = t / (256 * 128);
    int r = t % (256 * 128);
    int k = r / 128, j = r % 128;
    float v;
    if (k < 128) v = gcw[i * 16384 + j * 128 + k];
    else         v = biw[i * 16384 + j * 128 + (k - 128)];
    g_wcat[t] = v;
    if (k == 0) g_bias[i * 128 + j] = gcb[i * 128 + j] + bib[i * 128 + j];
}

// ---------------- init: ego0 = emb, all_embs[:, :128] = emb ----------------
__global__ void init_kernel(const float* __restrict__ emb, int N) {
    int t = blockIdx.x * blockDim.x + threadIdx.x;
    int total = N * 32;  // float4 per row = 32
    if (t >= total) return;
    int n = t / 32, f = t % 32;
    float4 v = ((const float4*)emb)[t];
    ((float4*)g_ego[0])[t] = v;
    ((float4*)g_all)[(size_t)n * 128 + f] = v;  // 512 floats = 128 float4 per row, segment 0
}

// ---------------- zero msg ----------------
__global__ void zero_kernel(int N) {
    int total = N * 32;
    float4 z = make_float4(0.f, 0.f, 0.f, 0.f);
    for (int t = blockIdx.x * blockDim.x + threadIdx.x; t < total; t += gridDim.x * blockDim.x)
        ((float4*)g_msg)[t] = z;
}

// ---------------- scatter: msg[row] += w * ego[col]  (warp per edge) ----------------
__global__ void scatter_kernel(const int* __restrict__ ei, const float* __restrict__ wt,
                               int sel, int E) {
    int g = blockIdx.x * blockDim.x + threadIdx.x;
    int e = g >> 5;
    if (e >= E) return;
    int lane = g & 31;
    int row = __ldg(ei + e);
    int col = __ldg(ei + E + e);
    float w = __ldg(wt + e);
    const float* ego = g_ego[sel];
    float4 v = __ldg((const float4*)(ego + (size_t)col * DIM) + lane);
    v.x *= w; v.y *= w; v.z *= w; v.w *= w;
    float* p = g_msg + (size_t)row * DIM + lane * 4;
    asm volatile("red.global.add.v4.f32 [%0], {%1,%2,%3,%4};"
                 :: "l"(p), "f"(v.x), "f"(v.y), "f"(v.z), "f"(v.w) : "memory");
}

// ---------------- fused layer GEMM: out = leakyrelu([msg, ego*msg] @ Wcat + bias) ----------------
// BM=64 nodes, BN=128 (full), BK=32. 256 threads, thread tile 8x4.
__global__ __launch_bounds__(256) void layer_kernel(int sel, int layer, int N) {
    __shared__ float As[64][33];    // [m][k] padded
    __shared__ float Bs[32][128];   // [k][j]

    const float* __restrict__ ego = g_ego[sel];
    const float* __restrict__ msg = g_msg;
    float* __restrict__ ego_out = g_ego[sel ^ 1];
    const float* __restrict__ W = g_wcat + (size_t)layer * 256 * 128;
    const float* __restrict__ bias = g_bias + layer * 128;

    int tid = threadIdx.x;
    int n0 = blockIdx.x * 64;
    int mi = tid >> 5;   // warp id, 8 row-groups
    int ni = tid & 31;   // lane, 32 col-groups of 4

    float acc[8][4];
#pragma unroll
    for (int r = 0; r < 8; r++)
#pragma unroll
        for (int c = 0; c < 4; c++) acc[r][c] = 0.f;

    for (int kb = 0; kb < 256; kb += 32) {
        // ---- load A tile: H[n][kb..kb+31] ----
        int f = tid & 7;        // float4 slot in 32-wide k chunk
        int r0 = tid >> 3;      // row 0..31
#pragma unroll
        for (int h = 0; h < 2; h++) {
            int r = r0 + h * 32;
            int n = n0 + r;
            float4 v = make_float4(0.f, 0.f, 0.f, 0.f);
            if (n < N) {
                if (kb < 128) {
                    v = __ldg((const float4*)(msg + (size_t)n * DIM + kb) + f);
                } else {
                    float4 m4 = __ldg((const float4*)(msg + (size_t)n * DIM + (kb - 128)) + f);
                    float4 e4 = __ldg((const float4*)(ego + (size_t)n * DIM + (kb - 128)) + f);
                    v.x = m4.x * e4.x; v.y = m4.y * e4.y; v.z = m4.z * e4.z; v.w = m4.w * e4.w;
                }
            }
            As[r][f * 4 + 0] = v.x;
            As[r][f * 4 + 1] = v.y;
            As[r][f * 4 + 2] = v.z;
            As[r][f * 4 + 3] = v.w;
        }
        // ---- load B tile: W[kb+kk][j], 4096 floats ----
#pragma unroll
        for (int it = 0; it < 4; it++) {
            int lin = it * 1024 + tid * 4;
            int kk = lin >> 7, j = lin & 127;
            *(float4*)&Bs[kk][j] = __ldg((const float4*)(W + (size_t)(kb + kk) * 128 + j));
        }
        __syncthreads();

#pragma unroll
        for (int kk = 0; kk < 32; kk++) {
            float4 b = *(const float4*)&Bs[kk][ni * 4];
#pragma unroll
            for (int r = 0; r < 8; r++) {
                float a = As[mi * 8 + r][kk];
                acc[r][0] += a * b.x;
                acc[r][1] += a * b.y;
                acc[r][2] += a * b.z;
                acc[r][3] += a * b.w;
            }
        }
        __syncthreads();
    }

    // ---- epilogue: bias, leaky relu, L2 normalize, write ego_out + all_embs ----
    float4 bv = __ldg((const float4*)bias + ni);
    int seg = (layer + 1) * 128;
#pragma unroll
    for (int r = 0; r < 8; r++) {
        int n = n0 + mi * 8 + r;
        if (n >= N) continue;    // uniform across warp (n independent of lane)
        float o0 = acc[r][0] + bv.x;
        float o1 = acc[r][1] + bv.y;
        float o2 = acc[r][2] + bv.z;
        float o3 = acc[r][3] + bv.w;
        o0 = o0 > 0.f ? o0 : 0.2f * o0;
        o1 = o1 > 0.f ? o1 : 0.2f * o1;
        o2 = o2 > 0.f ? o2 : 0.2f * o2;
        o3 = o3 > 0.f ? o3 : 0.2f * o3;
        float sq = o0 * o0 + o1 * o1 + o2 * o2 + o3 * o3;
#pragma unroll
        for (int off = 16; off > 0; off >>= 1)
            sq += __shfl_xor_sync(0xffffffffu, sq, off);
        float nrm = sqrtf(sq);
        float scale = 1.0f / fmaxf(nrm, 1e-12f);
        float4 ov = make_float4(o0, o1, o2, o3);
        ((float4*)(ego_out + (size_t)n * DIM))[ni] = ov;
        float4 sv = make_float4(o0 * scale, o1 * scale, o2 * scale, o3 * scale);
        ((float4*)(g_all + (size_t)n * 512 + seg))[ni] = sv;
    }
}

// ---------------- scoring: out[q] = dot(all[src], all[dst]) over 512 ----------------
__global__ void score_kernel(const int* __restrict__ eli, float* __restrict__ out, int Q) {
    int g = blockIdx.x * blockDim.x + threadIdx.x;
    int q = g >> 5;
    if (q >= Q) return;
    int lane = g & 31;
    int s = __ldg(eli + q);
    int d = __ldg(eli + Q + q);
    const float4* ps = (const float4*)(g_all + (size_t)s * 512);
    const float4* pd = (const float4*)(g_all + (size_t)d * 512);
    float sum = 0.f;
#pragma unroll
    for (int t = 0; t < 4; t++) {
        float4 a = __ldg(ps + lane + 32 * t);
        float4 b = __ldg(pd + lane + 32 * t);
        sum += a.x * b.x + a.y * b.y + a.z * b.z + a.w * b.w;
    }
#pragma unroll
    for (int off = 16; off > 0; off >>= 1)
        sum += __shfl_xor_sync(0xffffffffu, sum, off);
    if (lane == 0) out[q] = sum;
}

// ---------------- launch ----------------
extern "C" void kernel_launch(void* const* d_in, const int* in_sizes, int n_in,
                              void* d_out, int out_size) {
    const int*   ei  = (const int*)d_in[0];   // edge_index [2,E]
    const int*   eli = (const int*)d_in[1];   // edge_label_index [2,Q]
    const float* wt  = (const float*)d_in[2]; // edge_weight [E]
    const float* emb = (const float*)d_in[3]; // [N,128]
    const float* gcw = (const float*)d_in[4]; // [3,128,128]
    const float* gcb = (const float*)d_in[5]; // [3,128]
    const float* biw = (const float*)d_in[6]; // [3,128,128]
    const float* bib = (const float*)d_in[7]; // [3,128]

    int E = in_sizes[2];
    int Q = in_sizes[1] / 2;
    int N = in_sizes[3] / DIM;

    prep_kernel<<<(3 * 256 * 128 + 255) / 256, 256>>>(gcw, gcb, biw, bib);
    init_kernel<<<(N * 32 + 255) / 256, 256>>>(emb, N);

    int sel = 0;
    for (int i = 0; i < 3; i++) {
        zero_kernel<<<2048, 256>>>(N);
        long long sthreads = (long long)E * 32;
        int sblocks = (int)((sthreads + 255) / 256);
        scatter_kernel<<<sblocks, 256>>>(ei, wt, sel, E);
        layer_kernel<<<(N + 63) / 64, 256>>>(sel, i, N);
        sel ^= 1;
    }
    score_kernel<<<(Q * 32 + 255) / 256, 256>>>(eli, (float*)d_out, Q);
}

// round 2
// speedup vs baseline: 1.5109x; 1.5109x over previous
#include <cuda_runtime.h>
#include <cstdint>

#define MAXN 100000
#define MAXE 1600000
#define DIM 128

// ---------------- device scratch (no allocations allowed) ----------------
__device__ float g_all[(size_t)MAXN * 512];        // [N][512] concat embeddings
__device__ float g_ego[2][(size_t)MAXN * DIM];     // ping-pong ego buffers
__device__ float g_msg[(size_t)MAXN * DIM];        // segment-sum result
__device__ float g_wcat[3 * 256 * 128];            // [layer][k][j] combined W (transposed)
__device__ float g_bias[3 * 128];                  // gc_b + bi_b
// CSR
__device__ int   g_deg[MAXN];
__device__ int   g_cur[MAXN];
__device__ int   g_off[MAXN + 1];
__device__ int   g_bsum[256];
__device__ int   g_ccol[MAXE];
__device__ float g_cw[MAXE];

// ---------------- prep: transpose/combine weights ----------------
__global__ void prep_kernel(const float* __restrict__ gcw, const float* __restrict__ gcb,
                            const float* __restrict__ biw, const float* __restrict__ bib) {
    int t = blockIdx.x * blockDim.x + threadIdx.x;
    if (t >= 3 * 256 * 128) return;
    int i = t / (256 * 128);
    int r = t % (256 * 128);
    int k = r / 128, j = r % 128;
    float v;
    if (k < 128) v = gcw[i * 16384 + j * 128 + k];
    else         v = biw[i * 16384 + j * 128 + (k - 128)];
    g_wcat[t] = v;
    if (k == 0) g_bias[i * 128 + j] = gcb[i * 128 + j] + bib[i * 128 + j];
}

// ---------------- init: ego0 = emb, all_embs[:, :128] = emb ----------------
__global__ void init_kernel(const float* __restrict__ emb, int N) {
    int t = blockIdx.x * blockDim.x + threadIdx.x;
    int total = N * 32;
    if (t >= total) return;
    int n = t / 32, f = t % 32;
    float4 v = ((const float4*)emb)[t];
    ((float4*)g_ego[0])[t] = v;
    ((float4*)g_all)[(size_t)n * 128 + f] = v;
}

// ---------------- CSR build ----------------
__global__ void csr_zero_kernel(int N) {
    for (int i = blockIdx.x * blockDim.x + threadIdx.x; i < N; i += gridDim.x * blockDim.x) {
        g_deg[i] = 0;
        g_cur[i] = 0;
    }
}

__global__ void csr_hist_kernel(const int* __restrict__ ei, int E) {
    for (int e = blockIdx.x * blockDim.x + threadIdx.x; e < E; e += gridDim.x * blockDim.x)
        atomicAdd(&g_deg[ei[e]], 1);
}

__global__ void csr_scan_local_kernel(int N) {
    __shared__ int sm[1024];
    int b = blockIdx.x, t = threadIdx.x;
    int i = b * 1024 + t;
    int v = (i < N) ? g_deg[i] : 0;
    sm[t] = v;
    __syncthreads();
#pragma unroll
    for (int off = 1; off < 1024; off <<= 1) {
        int x = sm[t];
        int y = (t >= off) ? sm[t - off] : 0;
        __syncthreads();
        sm[t] = x + y;
        __syncthreads();
    }
    if (i < N) g_off[i] = sm[t] - v;  // exclusive
    if (t == 1023) g_bsum[b] = sm[t];
}

__global__ void csr_scan_bsum_kernel(int nblk) {
    __shared__ int sm[256];
    int t = threadIdx.x;
    int v = (t < nblk) ? g_bsum[t] : 0;
    sm[t] = v;
    __syncthreads();
#pragma unroll
    for (int off = 1; off < 256; off <<= 1) {
        int x = sm[t];
        int y = (t >= off) ? sm[t - off] : 0;
        __syncthreads();
        sm[t] = x + y;
        __syncthreads();
    }
    g_bsum[t] = sm[t] - v;  // exclusive
}

__global__ void csr_scan_add_kernel(int N, int E) {
    int i = blockIdx.x * blockDim.x + threadIdx.x;
    if (i < N) g_off[i] += g_bsum[i >> 10];
    if (i == 0) g_off[N] = E;
}

__global__ void csr_fill_kernel(const int* __restrict__ ei, const float* __restrict__ wt, int E) {
    for (int e = blockIdx.x * blockDim.x + threadIdx.x; e < E; e += gridDim.x * blockDim.x) {
        int row = ei[e];
        int pos = g_off[row] + atomicAdd(&g_cur[row], 1);
        g_ccol[pos] = ei[E + e];
        g_cw[pos] = wt[e];
    }
}

// ---------------- gather: msg[n] = sum_e w * ego[col]  (warp per node) ----------------
__global__ void gather_kernel(int sel, int N) {
    int g = blockIdx.x * blockDim.x + threadIdx.x;
    int n = g >> 5;
    if (n >= N) return;
    int lane = g & 31;
    int s = g_off[n], e = g_off[n + 1];
    const float* __restrict__ ego = g_ego[sel];
    float4 acc = make_float4(0.f, 0.f, 0.f, 0.f);
    int i = s;
    for (; i + 4 <= e; i += 4) {
        int c0 = __ldg(g_ccol + i), c1 = __ldg(g_ccol + i + 1);
        int c2 = __ldg(g_ccol + i + 2), c3 = __ldg(g_ccol + i + 3);
        float w0 = __ldg(g_cw + i), w1 = __ldg(g_cw + i + 1);
        float w2 = __ldg(g_cw + i + 2), w3 = __ldg(g_cw + i + 3);
        float4 v0 = __ldg((const float4*)(ego + (size_t)c0 * DIM) + lane);
        float4 v1 = __ldg((const float4*)(ego + (size_t)c1 * DIM) + lane);
        float4 v2 = __ldg((const float4*)(ego + (size_t)c2 * DIM) + lane);
        float4 v3 = __ldg((const float4*)(ego + (size_t)c3 * DIM) + lane);
        acc.x += w0 * v0.x; acc.y += w0 * v0.y; acc.z += w0 * v0.z; acc.w += w0 * v0.w;
        acc.x += w1 * v1.x; acc.y += w1 * v1.y; acc.z += w1 * v1.z; acc.w += w1 * v1.w;
        acc.x += w2 * v2.x; acc.y += w2 * v2.y; acc.z += w2 * v2.z; acc.w += w2 * v2.w;
        acc.x += w3 * v3.x; acc.y += w3 * v3.y; acc.z += w3 * v3.z; acc.w += w3 * v3.w;
    }
    for (; i < e; i++) {
        int c = __ldg(g_ccol + i);
        float w = __ldg(g_cw + i);
        float4 v = __ldg((const float4*)(ego + (size_t)c * DIM) + lane);
        acc.x += w * v.x; acc.y += w * v.y; acc.z += w * v.z; acc.w += w * v.w;
    }
    ((float4*)(g_msg + (size_t)n * DIM))[lane] = acc;
}

// ---------------- fused layer GEMM: out = leakyrelu([msg, ego*msg] @ Wcat + bias) ----------------
// BM=128, BN=128, BK=16. 256 threads, thread tile 8x8.
__global__ __launch_bounds__(256) void layer_kernel(int sel, int layer, int N) {
    __shared__ float As[16][128];   // [k][m]
    __shared__ float Bs[16][128];   // [k][j]

    const float* __restrict__ ego = g_ego[sel];
    const float* __restrict__ msg = g_msg;
    float* __restrict__ ego_out = g_ego[sel ^ 1];
    const float* __restrict__ W = g_wcat + (size_t)layer * 256 * 128;
    const float* __restrict__ bias = g_bias + layer * 128;

    int tid = threadIdx.x;
    int n0 = blockIdx.x * 128;
    int ty = tid >> 4;    // 0..15 -> rows ty*8..ty*8+7
    int tx = tid & 15;    // 0..15 -> cols tx*4..+3 and +64

    int arow = tid & 127;     // A-load row
    int afq = tid >> 7;       // 0/1 -> k-quad base

    float acc[8][8];
#pragma unroll
    for (int r = 0; r < 8; r++)
#pragma unroll
        for (int c = 0; c < 8; c++) acc[r][c] = 0.f;

    int nA = n0 + arow;
    bool validA = nA < N;

    for (int kb = 0; kb < 256; kb += 16) {
        // ---- A tile: H[n][kb..kb+15] -> As[k][m] ----
#pragma unroll
        for (int h = 0; h < 2; h++) {
            int kk = afq * 4 + h * 8;
            int kglob = kb + kk;
            float4 v = make_float4(0.f, 0.f, 0.f, 0.f);
            if (validA) {
                if (kglob < 128) {
                    v = __ldg((const float4*)(msg + (size_t)nA * DIM + kglob));
                } else {
                    float4 m4 = __ldg((const float4*)(msg + (size_t)nA * DIM + (kglob - 128)));
                    float4 e4 = __ldg((const float4*)(ego + (size_t)nA * DIM + (kglob - 128)));
                    v.x = m4.x * e4.x; v.y = m4.y * e4.y; v.z = m4.z * e4.z; v.w = m4.w * e4.w;
                }
            }
            As[kk + 0][arow] = v.x;
            As[kk + 1][arow] = v.y;
            As[kk + 2][arow] = v.z;
            As[kk + 3][arow] = v.w;
        }
        // ---- B tile: W[kb+kk][j] ----
#pragma unroll
        for (int h = 0; h < 2; h++) {
            int lin = tid * 4 + h * 1024;
            int kk = lin >> 7, j = lin & 127;
            *(float4*)&Bs[kk][j] = __ldg((const float4*)(W + (size_t)(kb + kk) * 128 + j));
        }
        __syncthreads();

#pragma unroll
        for (int kk = 0; kk < 16; kk++) {
            float4 a0 = *(const float4*)&As[kk][ty * 8];
            float4 a1 = *(const float4*)&As[kk][ty * 8 + 4];
            float4 b0 = *(const float4*)&Bs[kk][tx * 4];
            float4 b1 = *(const float4*)&Bs[kk][tx * 4 + 64];
            float a[8] = {a0.x, a0.y, a0.z, a0.w, a1.x, a1.y, a1.z, a1.w};
            float b[8] = {b0.x, b0.y, b0.z, b0.w, b1.x, b1.y, b1.z, b1.w};
#pragma unroll
            for (int r = 0; r < 8; r++)
#pragma unroll
                for (int c = 0; c < 8; c++)
                    acc[r][c] += a[r] * b[c];
        }
        __syncthreads();
    }

    // ---- epilogue: bias, leaky relu, L2 normalize, write ----
    float4 bv0 = __ldg((const float4*)bias + tx);
    float4 bv1 = __ldg((const float4*)bias + tx + 16);
    int seg = (layer + 1) * 128;
#pragma unroll
    for (int r = 0; r < 8; r++) {
        int n = n0 + ty * 8 + r;
        float o[8];
        o[0] = acc[r][0] + bv0.x; o[1] = acc[r][1] + bv0.y;
        o[2] = acc[r][2] + bv0.z; o[3] = acc[r][3] + bv0.w;
        o[4] = acc[r][4] + bv1.x; o[5] = acc[r][5] + bv1.y;
        o[6] = acc[r][6] + bv1.z; o[7] = acc[r][7] + bv1.w;
        float sq = 0.f;
#pragma unroll
        for (int c = 0; c < 8; c++) {
            o[c] = o[c] > 0.f ? o[c] : 0.2f * o[c];
            sq += o[c] * o[c];
        }
#pragma unroll
        for (int off = 1; off < 16; off <<= 1)
            sq += __shfl_xor_sync(0xffffffffu, sq, off);
        float scale = 1.0f / fmaxf(sqrtf(sq), 1e-12f);
        if (n < N) {
            float4 ov0 = make_float4(o[0], o[1], o[2], o[3]);
            float4 ov1 = make_float4(o[4], o[5], o[6], o[7]);
            ((float4*)(ego_out + (size_t)n * DIM))[tx] = ov0;
            ((float4*)(ego_out + (size_t)n * DIM))[tx + 16] = ov1;
            float4 sv0 = make_float4(o[0] * scale, o[1] * scale, o[2] * scale, o[3] * scale);
            float4 sv1 = make_float4(o[4] * scale, o[5] * scale, o[6] * scale, o[7] * scale);
            ((float4*)(g_all + (size_t)n * 512 + seg))[tx] = sv0;
            ((float4*)(g_all + (size_t)n * 512 + seg))[tx + 16] = sv1;
        }
    }
}

// ---------------- scoring: out[q] = dot(all[src], all[dst]) over 512 ----------------
__global__ void score_kernel(const int* __restrict__ eli, float* __restrict__ out, int Q) {
    int g = blockIdx.x * blockDim.x + threadIdx.x;
    int q = g >> 5;
    if (q >= Q) return;
    int lane = g & 31;
    int s = __ldg(eli + q);
    int d = __ldg(eli + Q + q);
    const float4* ps = (const float4*)(g_all + (size_t)s * 512);
    const float4* pd = (const float4*)(g_all + (size_t)d * 512);
    float sum = 0.f;
#pragma unroll
    for (int t = 0; t < 4; t++) {
        float4 a = __ldg(ps + lane + 32 * t);
        float4 b = __ldg(pd + lane + 32 * t);
        sum += a.x * b.x + a.y * b.y + a.z * b.z + a.w * b.w;
    }
#pragma unroll
    for (int off = 16; off > 0; off >>= 1)
        sum += __shfl_xor_sync(0xffffffffu, sum, off);
    if (lane == 0) out[q] = sum;
}

// ---------------- launch ----------------
extern "C" void kernel_launch(void* const* d_in, const int* in_sizes, int n_in,
                              void* d_out, int out_size) {
    const int*   ei  = (const int*)d_in[0];   // edge_index [2,E]
    const int*   eli = (const int*)d_in[1];   // edge_label_index [2,Q]
    const float* wt  = (const float*)d_in[2]; // edge_weight [E]
    const float* emb = (const float*)d_in[3]; // [N,128]
    const float* gcw = (const float*)d_in[4]; // [3,128,128]
    const float* gcb = (const float*)d_in[5]; // [3,128]
    const float* biw = (const float*)d_in[6]; // [3,128,128]
    const float* bib = (const float*)d_in[7]; // [3,128]

    int E = in_sizes[2];
    int Q = in_sizes[1] / 2;
    int N = in_sizes[3] / DIM;

    prep_kernel<<<(3 * 256 * 128 + 255) / 256, 256>>>(gcw, gcb, biw, bib);
    init_kernel<<<(N * 32 + 255) / 256, 256>>>(emb, N);

    // CSR build (once per launch)
    int nblk = (N + 1023) / 1024;
    csr_zero_kernel<<<256, 256>>>(N);
    csr_hist_kernel<<<1024, 256>>>(ei, E);
    csr_scan_local_kernel<<<nblk, 1024>>>(N);
    csr_scan_bsum_kernel<<<1, 256>>>(nblk);
    csr_scan_add_kernel<<<(N + 255) / 256, 256>>>(N, E);
    csr_fill_kernel<<<1024, 256>>>(ei, wt, E);

    int sel = 0;
    for (int i = 0; i < 3; i++) {
        long long gthreads = (long long)N * 32;
        int gblocks = (int)((gthreads + 255) / 256);
        gather_kernel<<<gblocks, 256>>>(sel, N);
        layer_kernel<<<(N + 127) / 128, 256>>>(sel, i, N);
        sel ^= 1;
    }
    score_kernel<<<(Q * 32 + 255) / 256, 256>>>(eli, (float*)d_out, Q);
}

// round 4
// speedup vs baseline: 1.8769x; 1.2422x over previous
#include <cuda_runtime.h>
#include <cuda_bf16.h>
#include <cstdint>

#define MAXN 100000
#define MAXE 1600000
#define DIM 128

// ---------------- device scratch (no allocations allowed) ----------------
__device__ float g_all[(size_t)MAXN * 512];        // [N][512] concat embeddings
__device__ float g_ego[2][(size_t)MAXN * DIM];     // ping-pong ego buffers (unnormalized)
__device__ float g_msg[(size_t)MAXN * DIM];        // segment-sum result
__device__ __nv_bfloat16 g_wbf_hi[3 * 128 * 256];  // [layer][j][k] combined W rows, bf16 hi
__device__ __nv_bfloat16 g_wbf_lo[3 * 128 * 256];  // bf16 lo (residual)
__device__ float g_bias[3 * 128];                  // gc_b + bi_b
// CSR
__device__ int   g_deg[MAXN];
__device__ int   g_cur[MAXN];
__device__ int   g_off[MAXN + 1];
__device__ int   g_bsum[256];
__device__ int   g_ccol[MAXE];
__device__ float g_cw[MAXE];

// ================= helpers =================
__device__ __forceinline__ uint32_t smem_u32(const void* p) {
    uint32_t a;
    asm("{ .reg .u64 t; cvta.to.shared.u64 t, %1; cvt.u32.u64 %0, t; }" : "=r"(a) : "l"(p));
    return a;
}
#define LDSM_X4(r, addr) \
    asm volatile("ldmatrix.sync.aligned.m8n8.x4.shared.b16 {%0,%1,%2,%3}, [%4];" \
        : "=r"((r)[0]), "=r"((r)[1]), "=r"((r)[2]), "=r"((r)[3]) : "r"(addr))

__device__ __forceinline__ void mma16816(float* c, const uint32_t* a, const uint32_t* b) {
    asm volatile("mma.sync.aligned.m16n8k16.row.col.f32.bf16.bf16.f32 "
        "{%0,%1,%2,%3}, {%4,%5,%6,%7}, {%8,%9}, {%0,%1,%2,%3};"
        : "+f"(c[0]), "+f"(c[1]), "+f"(c[2]), "+f"(c[3])
        : "r"(a[0]), "r"(a[1]), "r"(a[2]), "r"(a[3]), "r"(b[0]), "r"(b[1]));
}

// ---------------- prep: combined W rows -> bf16 hi/lo, bias ----------------
__global__ void prep_kernel(const float* __restrict__ gcw, const float* __restrict__ gcb,
                            const float* __restrict__ biw, const float* __restrict__ bib) {
    int t = blockIdx.x * blockDim.x + threadIdx.x;
    if (t >= 3 * 128 * 256) return;
    int i = t >> 15;
    int r = t & 32767;
    int j = r >> 8, k = r & 255;
    float v;
    if (k < 128) v = gcw[i * 16384 + j * 128 + k];
    else         v = biw[i * 16384 + j * 128 + (k - 128)];
    __nv_bfloat16 hi = __float2bfloat16_rn(v);
    __nv_bfloat16 lo = __float2bfloat16_rn(v - __bfloat162float(hi));
    g_wbf_hi[t] = hi;
    g_wbf_lo[t] = lo;
    if (k == 0) g_bias[i * 128 + j] = gcb[i * 128 + j] + bib[i * 128 + j];
}

// ---------------- init ----------------
__global__ void init_kernel(const float* __restrict__ emb, int N) {
    int t = blockIdx.x * blockDim.x + threadIdx.x;
    int total = N * 32;
    if (t >= total) return;
    int n = t / 32, f = t % 32;
    float4 v = ((const float4*)emb)[t];
    ((float4*)g_ego[0])[t] = v;
    ((float4*)g_all)[(size_t)n * 128 + f] = v;
}

// ---------------- CSR build ----------------
__global__ void csr_zero_kernel(int N) {
    for (int i = blockIdx.x * blockDim.x + threadIdx.x; i < N; i += gridDim.x * blockDim.x) {
        g_deg[i] = 0;
        g_cur[i] = 0;
    }
}
__global__ void csr_hist_kernel(const int* __restrict__ ei, int E) {
    for (int e = blockIdx.x * blockDim.x + threadIdx.x; e < E; e += gridDim.x * blockDim.x)
        atomicAdd(&g_deg[ei[e]], 1);
}
__global__ void csr_scan_local_kernel(int N) {
    __shared__ int sm[1024];
    int b = blockIdx.x, t = threadIdx.x;
    int i = b * 1024 + t;
    int v = (i < N) ? g_deg[i] : 0;
    sm[t] = v;
    __syncthreads();
#pragma unroll
    for (int off = 1; off < 1024; off <<= 1) {
        int x = sm[t];
        int y = (t >= off) ? sm[t - off] : 0;
        __syncthreads();
        sm[t] = x + y;
        __syncthreads();
    }
    if (i < N) g_off[i] = sm[t] - v;
    if (t == 1023) g_bsum[b] = sm[t];
}
__global__ void csr_scan_bsum_kernel(int nblk) {
    __shared__ int sm[256];
    int t = threadIdx.x;
    int v = (t < nblk) ? g_bsum[t] : 0;
    sm[t] = v;
    __syncthreads();
#pragma unroll
    for (int off = 1; off < 256; off <<= 1) {
        int x = sm[t];
        int y = (t >= off) ? sm[t - off] : 0;
        __syncthreads();
        sm[t] = x + y;
        __syncthreads();
    }
    g_bsum[t] = sm[t] - v;
}
__global__ void csr_scan_add_kernel(int N, int E) {
    int i = blockIdx.x * blockDim.x + threadIdx.x;
    if (i < N) g_off[i] += g_bsum[i >> 10];
    if (i == 0) g_off[N] = E;
}
__global__ void csr_fill_kernel(const int* __restrict__ ei, const float* __restrict__ wt, int E) {
    for (int e = blockIdx.x * blockDim.x + threadIdx.x; e < E; e += gridDim.x * blockDim.x) {
        int row = ei[e];
        int pos = g_off[row] + atomicAdd(&g_cur[row], 1);
        g_ccol[pos] = ei[E + e];
        g_cw[pos] = wt[e];
    }
}

// ---------------- gather: msg[n] = sum_e w * ego[col]  (warp per node) ----------------
__global__ void gather_kernel(int sel, int N) {
    int g = blockIdx.x * blockDim.x + threadIdx.x;
    int n = g >> 5;
    if (n >= N) return;
    int lane = g & 31;
    int s = g_off[n], e = g_off[n + 1];
    const float* __restrict__ ego = g_ego[sel];
    float4 acc = make_float4(0.f, 0.f, 0.f, 0.f);
    int i = s;
    for (; i + 4 <= e; i += 4) {
        int c0 = __ldg(g_ccol + i), c1 = __ldg(g_ccol + i + 1);
        int c2 = __ldg(g_ccol + i + 2), c3 = __ldg(g_ccol + i + 3);
        float w0 = __ldg(g_cw + i), w1 = __ldg(g_cw + i + 1);
        float w2 = __ldg(g_cw + i + 2), w3 = __ldg(g_cw + i + 3);
        float4 v0 = __ldg((const float4*)(ego + (size_t)c0 * DIM) + lane);
        float4 v1 = __ldg((const float4*)(ego + (size_t)c1 * DIM) + lane);
        float4 v2 = __ldg((const float4*)(ego + (size_t)c2 * DIM) + lane);
        float4 v3 = __ldg((const float4*)(ego + (size_t)c3 * DIM) + lane);
        acc.x += w0 * v0.x; acc.y += w0 * v0.y; acc.z += w0 * v0.z; acc.w += w0 * v0.w;
        acc.x += w1 * v1.x; acc.y += w1 * v1.y; acc.z += w1 * v1.z; acc.w += w1 * v1.w;
        acc.x += w2 * v2.x; acc.y += w2 * v2.y; acc.z += w2 * v2.z; acc.w += w2 * v2.w;
        acc.x += w3 * v3.x; acc.y += w3 * v3.y; acc.z += w3 * v3.z; acc.w += w3 * v3.w;
    }
    for (; i < e; i++) {
        int c = __ldg(g_ccol + i);
        float w = __ldg(g_cw + i);
        float4 v = __ldg((const float4*)(ego + (size_t)c * DIM) + lane);
        acc.x += w * v.x; acc.y += w * v.y; acc.z += w * v.z; acc.w += w * v.w;
    }
    ((float4*)(g_msg + (size_t)n * DIM))[lane] = acc;
}

// ================= layer GEMM via mma.sync bf16 (split-bf16 x3) =================
// out[n][j] = leakyrelu( sum_k H[n][k]*Wcat[k][j] + bias[j] ), H = [msg | ego*msg]
// Block: 128x128, K=256 in 4 stages of 64. 256 threads (8 warps, warp tile 64x32).
// SMEM tiles: Ahi/Alo/Bhi/Blo each [128 rows][8 chunks of 16B] swizzled c^= (r&7).
#define TILE_AHI 0
#define TILE_ALO 16384
#define TILE_BHI 32768
#define TILE_BLO 49152
#define EPI_STAGE 0          // float stage[128][136]
#define EPI_ROWPART 69632    // float [128][4]
#define EPI_SCALE 71680      // float [128]
#define LK_SMEM 72192

__global__ __launch_bounds__(256, 1) void layer_kernel(int sel, int layer, int N) {
    extern __shared__ char smem[];
    const uint32_t sb = smem_u32(smem);
    const int tid = threadIdx.x;
    const int wid = tid >> 5;
    const int lid = tid & 31;
    const int n0 = blockIdx.x * 128;
    const int wm = wid >> 2;       // 0..1   rows wm*64
    const int wn = wid & 3;        // 0..3   cols wn*32

    const float* __restrict__ msg = g_msg;
    const float* __restrict__ ego = g_ego[sel];
    const __nv_bfloat16* __restrict__ wbh = g_wbf_hi + (size_t)layer * 32768;
    const __nv_bfloat16* __restrict__ wbl = g_wbf_lo + (size_t)layer * 32768;

    float acc[4][4][4];
#pragma unroll
    for (int mt = 0; mt < 4; mt++)
#pragma unroll
        for (int nt = 0; nt < 4; nt++)
#pragma unroll
            for (int c = 0; c < 4; c++) acc[mt][nt][c] = 0.f;

    for (int kb = 0; kb < 4; kb++) {
        __syncthreads();
        // ---- A: 1024 chunk-tasks (row 0..127, chunk 0..7), 8 floats each ----
#pragma unroll
        for (int it = 0; it < 4; it++) {
            int i = tid + 256 * it;
            int row = i >> 3, c = i & 7;
            int kg = kb * 64 + c * 8;
            int n = n0 + row;
            float4 v0 = make_float4(0.f, 0.f, 0.f, 0.f);
            float4 v1 = v0;
            if (n < N) {
                if (kg < 128) {
                    v0 = __ldg((const float4*)(msg + (size_t)n * DIM + kg));
                    v1 = __ldg((const float4*)(msg + (size_t)n * DIM + kg + 4));
                } else {
                    float4 m0 = __ldg((const float4*)(msg + (size_t)n * DIM + kg - 128));
                    float4 m1 = __ldg((const float4*)(msg + (size_t)n * DIM + kg - 124));
                    float4 e0 = __ldg((const float4*)(ego + (size_t)n * DIM + kg - 128));
                    float4 e1 = __ldg((const float4*)(ego + (size_t)n * DIM + kg - 124));
                    v0.x = m0.x * e0.x; v0.y = m0.y * e0.y; v0.z = m0.z * e0.z; v0.w = m0.w * e0.w;
                    v1.x = m1.x * e1.x; v1.y = m1.y * e1.y; v1.z = m1.z * e1.z; v1.w = m1.w * e1.w;
                }
            }
            // split to hi/lo bf16x8 (16B each)
            __nv_bfloat162 h0 = __floats2bfloat162_rn(v0.x, v0.y);
            __nv_bfloat162 h1 = __floats2bfloat162_rn(v0.z, v0.w);
            __nv_bfloat162 h2 = __floats2bfloat162_rn(v1.x, v1.y);
            __nv_bfloat162 h3 = __floats2bfloat162_rn(v1.z, v1.w);
            __nv_bfloat162 l0 = __floats2bfloat162_rn(v0.x - __bfloat162float(h0.x), v0.y - __bfloat162float(h0.y));
            __nv_bfloat162 l1 = __floats2bfloat162_rn(v0.z - __bfloat162float(h1.x), v0.w - __bfloat162float(h1.y));
            __nv_bfloat162 l2 = __floats2bfloat162_rn(v1.x - __bfloat162float(h2.x), v1.y - __bfloat162float(h2.y));
            __nv_bfloat162 l3 = __floats2bfloat162_rn(v1.z - __bfloat162float(h3.x), v1.w - __bfloat162float(h3.y));
            int ci = row * 8 + (c ^ (row & 7));
            uint4 hw, lw;
            hw.x = *(uint32_t*)&h0; hw.y = *(uint32_t*)&h1; hw.z = *(uint32_t*)&h2; hw.w = *(uint32_t*)&h3;
            lw.x = *(uint32_t*)&l0; lw.y = *(uint32_t*)&l1; lw.z = *(uint32_t*)&l2; lw.w = *(uint32_t*)&l3;
            ((uint4*)(smem + TILE_AHI))[ci] = hw;
            ((uint4*)(smem + TILE_ALO))[ci] = lw;
        }
        // ---- B: preconverted bf16 hi/lo, just copy swizzled ----
#pragma unroll
        for (int it = 0; it < 4; it++) {
            int i = tid + 256 * it;
            int row = i >> 3, c = i & 7;
            int kg = kb * 64 + c * 8;
            uint4 hw = __ldg((const uint4*)(wbh + (size_t)row * 256 + kg));
            uint4 lw = __ldg((const uint4*)(wbl + (size_t)row * 256 + kg));
            int ci = row * 8 + (c ^ (row & 7));
            ((uint4*)(smem + TILE_BHI))[ci] = hw;
            ((uint4*)(smem + TILE_BLO))[ci] = lw;
        }
        __syncthreads();

        // ---- compute: 4 k16 steps ----
#pragma unroll
        for (int ks = 0; ks < 4; ks++) {
            uint32_t ahi[4][4], alo[4][4];
            int lr = lid & 15, lk = lid >> 4;
#pragma unroll
            for (int mt = 0; mt < 4; mt++) {
                int r = wm * 64 + mt * 16 + lr;
                int kc = ks * 2 + lk;
                uint32_t off = (uint32_t)(r * 8 + (kc ^ (r & 7))) * 16;
                LDSM_X4(ahi[mt], sb + TILE_AHI + off);
                LDSM_X4(alo[mt], sb + TILE_ALO + off);
            }
            uint32_t bhi[2][4], blo[2][4];
            int nr = (lid & 7) + ((lid >> 4) << 3);
            int nk = (lid >> 3) & 1;
#pragma unroll
            for (int np = 0; np < 2; np++) {
                int r = wn * 32 + np * 16 + nr;
                int kc = ks * 2 + nk;
                uint32_t off = (uint32_t)(r * 8 + (kc ^ (r & 7))) * 16;
                LDSM_X4(bhi[np], sb + TILE_BHI + off);
                LDSM_X4(blo[np], sb + TILE_BLO + off);
            }
#pragma unroll
            for (int mt = 0; mt < 4; mt++)
#pragma unroll
                for (int nt = 0; nt < 4; nt++) {
                    const uint32_t* bh = &bhi[nt >> 1][(nt & 1) * 2];
                    const uint32_t* bl = &blo[nt >> 1][(nt & 1) * 2];
                    mma16816(acc[mt][nt], ahi[mt], bh);
                    mma16816(acc[mt][nt], ahi[mt], bl);
                    mma16816(acc[mt][nt], alo[mt], bh);
                }
        }
    }

    // ================= epilogue =================
    __syncthreads();
    float* stage = (float*)(smem + EPI_STAGE);        // [128][136]
    float* rowpart = (float*)(smem + EPI_ROWPART);    // [128][4]
    const float* bias = g_bias + layer * 128;
    int qid = lid >> 2, qt = lid & 3;
#pragma unroll
    for (int mt = 0; mt < 4; mt++) {
        int rA = wm * 64 + mt * 16 + qid;
        int rB = rA + 8;
        float sqa = 0.f, sqb = 0.f;
#pragma unroll
        for (int nt = 0; nt < 4; nt++) {
            int col = wn * 32 + nt * 8 + 2 * qt;
            float b0 = __ldg(bias + col), b1 = __ldg(bias + col + 1);
            float* c = acc[mt][nt];
            float x0 = c[0] + b0, x1 = c[1] + b1;
            float y0 = c[2] + b0, y1 = c[3] + b1;
            x0 = x0 > 0.f ? x0 : 0.2f * x0;
            x1 = x1 > 0.f ? x1 : 0.2f * x1;
            y0 = y0 > 0.f ? y0 : 0.2f * y0;
            y1 = y1 > 0.f ? y1 : 0.2f * y1;
            stage[rA * 136 + col] = x0;
            stage[rA * 136 + col + 1] = x1;
            stage[rB * 136 + col] = y0;
            stage[rB * 136 + col + 1] = y1;
            sqa += x0 * x0 + x1 * x1;
            sqb += y0 * y0 + y1 * y1;
        }
        sqa += __shfl_xor_sync(0xffffffffu, sqa, 1);
        sqa += __shfl_xor_sync(0xffffffffu, sqa, 2);
        sqb += __shfl_xor_sync(0xffffffffu, sqb, 1);
        sqb += __shfl_xor_sync(0xffffffffu, sqb, 2);
        if (qt == 0) {
            rowpart[rA * 4 + wn] = sqa;
            rowpart[rB * 4 + wn] = sqb;
        }
    }
    __syncthreads();
    float* scl = (float*)(smem + EPI_SCALE);
    if (tid < 128) {
        float tot = rowpart[tid * 4] + rowpart[tid * 4 + 1] + rowpart[tid * 4 + 2] + rowpart[tid * 4 + 3];
        scl[tid] = 1.0f / fmaxf(sqrtf(tot), 1e-12f);
    }
    __syncthreads();
    float* ego_out = g_ego[sel ^ 1];
    int seg = (layer + 1) * 128;
#pragma unroll
    for (int it = 0; it < 16; it++) {
        int idx = tid + 256 * it;   // [128 rows][32 f4]
        int r = idx >> 5, j = idx & 31;
        int n = n0 + r;
        if (n < N) {
            float4 v = *(const float4*)(stage + r * 136 + j * 4);
            ((float4*)(ego_out + (size_t)n * DIM))[j] = v;
            float s = scl[r];
            float4 sv = make_float4(v.x * s, v.y * s, v.z * s, v.w * s);
            ((float4*)(g_all + (size_t)n * 512 + seg))[j] = sv;
        }
    }
}

// ---------------- scoring ----------------
__global__ void score_kernel(const int* __restrict__ eli, float* __restrict__ out, int Q) {
    int g = blockIdx.x * blockDim.x + threadIdx.x;
    int q = g >> 5;
    if (q >= Q) return;
    int lane = g & 31;
    int s = __ldg(eli + q);
    int d = __ldg(eli + Q + q);
    const float4* ps = (const float4*)(g_all + (size_t)s * 512);
    const float4* pd = (const float4*)(g_all + (size_t)d * 512);
    float sum = 0.f;
#pragma unroll
    for (int t = 0; t < 4; t++) {
        float4 a = __ldg(ps + lane + 32 * t);
        float4 b = __ldg(pd + lane + 32 * t);
        sum += a.x * b.x + a.y * b.y + a.z * b.z + a.w * b.w;
    }
#pragma unroll
    for (int off = 16; off > 0; off >>= 1)
        sum += __shfl_xor_sync(0xffffffffu, sum, off);
    if (lane == 0) out[q] = sum;
}

// ---------------- launch ----------------
extern "C" void kernel_launch(void* const* d_in, const int* in_sizes, int n_in,
                              void* d_out, int out_size) {
    const int*   ei  = (const int*)d_in[0];
    const int*   eli = (const int*)d_in[1];
    const float* wt  = (const float*)d_in[2];
    const float* emb = (const float*)d_in[3];
    const float* gcw = (const float*)d_in[4];
    const float* gcb = (const float*)d_in[5];
    const float* biw = (const float*)d_in[6];
    const float* bib = (const float*)d_in[7];

    int E = in_sizes[2];
    int Q = in_sizes[1] / 2;
    int N = in_sizes[3] / DIM;

    static bool attr_set = false;
    if (!attr_set) {
        cudaFuncSetAttribute(layer_kernel, cudaFuncAttributeMaxDynamicSharedMemorySize, LK_SMEM);
        attr_set = true;
    }

    prep_kernel<<<(3 * 128 * 256 + 255) / 256, 256>>>(gcw, gcb, biw, bib);
    init_kernel<<<(N * 32 + 255) / 256, 256>>>(emb, N);

    int nblk = (N + 1023) / 1024;
    csr_zero_kernel<<<256, 256>>>(N);
    csr_hist_kernel<<<1024, 256>>>(ei, E);
    csr_scan_local_kernel<<<nblk, 1024>>>(N);
    csr_scan_bsum_kernel<<<1, 256>>>(nblk);
    csr_scan_add_kernel<<<(N + 255) / 256, 256>>>(N, E);
    csr_fill_kernel<<<1024, 256>>>(ei, wt, E);

    int sel = 0;
    for (int i = 0; i < 3; i++) {
        long long gthreads = (long long)N * 32;
        int gblocks = (int)((gthreads + 255) / 256);
        gather_kernel<<<gblocks, 256>>>(sel, N);
        layer_kernel<<<(N + 127) / 128, 256, LK_SMEM>>>(sel, i, N);
        sel ^= 1;
    }
    score_kernel<<<(Q * 32 + 255) / 256, 256>>>(eli, (float*)d_out, Q);
}

// round 5
// speedup vs baseline: 2.3938x; 1.2754x over previous
#include <cuda_runtime.h>
#include <cuda_bf16.h>
#include <cstdint>

#define MAXN 100000
#define MAXE 1600000
#define DIM 128

// ---------------- device scratch (no allocations allowed) ----------------
__device__ float g_all[(size_t)MAXN * 512];        // [N][512] concat embeddings
__device__ float g_ego[2][(size_t)MAXN * DIM];     // ping-pong ego buffers (unnormalized)
__device__ __nv_bfloat16 g_h_hi[(size_t)MAXN * 256];   // H=[msg|ego*msg] hi
__device__ __nv_bfloat16 g_h_lo[(size_t)MAXN * 256];   // H lo residual
__device__ __nv_bfloat16 g_wbf_hi[3 * 128 * 256];  // [layer][j][k] combined W rows, bf16 hi
__device__ __nv_bfloat16 g_wbf_lo[3 * 128 * 256];  // bf16 lo (residual)
__device__ float g_bias[3 * 128];                  // gc_b + bi_b
// CSR
__device__ int   g_deg[MAXN];
__device__ int   g_cur[MAXN];
__device__ int   g_off[MAXN + 1];
__device__ int   g_bsum[256];
__device__ int   g_ccol[MAXE];
__device__ float g_cw[MAXE];

// ================= helpers =================
__device__ __forceinline__ uint32_t smem_u32(const void* p) {
    uint32_t a;
    asm("{ .reg .u64 t; cvta.to.shared.u64 t, %1; cvt.u32.u64 %0, t; }" : "=r"(a) : "l"(p));
    return a;
}
#define LDSM_X4(r, addr) \
    asm volatile("ldmatrix.sync.aligned.m8n8.x4.shared.b16 {%0,%1,%2,%3}, [%4];" \
        : "=r"((r)[0]), "=r"((r)[1]), "=r"((r)[2]), "=r"((r)[3]) : "r"(addr))

__device__ __forceinline__ void mma16816(float* c, const uint32_t* a, const uint32_t* b) {
    asm volatile("mma.sync.aligned.m16n8k16.row.col.f32.bf16.bf16.f32 "
        "{%0,%1,%2,%3}, {%4,%5,%6,%7}, {%8,%9}, {%0,%1,%2,%3};"
        : "+f"(c[0]), "+f"(c[1]), "+f"(c[2]), "+f"(c[3])
        : "r"(a[0]), "r"(a[1]), "r"(a[2]), "r"(a[3]), "r"(b[0]), "r"(b[1]));
}
__device__ __forceinline__ void cp_async16(uint32_t smem, const void* g, uint32_t srcsize) {
    asm volatile("cp.async.cg.shared.global [%0], [%1], 16, %2;"
                 :: "r"(smem), "l"(g), "r"(srcsize) : "memory");
}
#define CP_COMMIT() asm volatile("cp.async.commit_group;" ::: "memory")
#define CP_WAIT1() asm volatile("cp.async.wait_group 1;" ::: "memory")
#define CP_WAIT0() asm volatile("cp.async.wait_group 0;" ::: "memory")

// ---------------- prep: combined W rows -> bf16 hi/lo, bias ----------------
__global__ void prep_kernel(const float* __restrict__ gcw, const float* __restrict__ gcb,
                            const float* __restrict__ biw, const float* __restrict__ bib) {
    int t = blockIdx.x * blockDim.x + threadIdx.x;
    if (t >= 3 * 128 * 256) return;
    int i = t >> 15;
    int r = t & 32767;
    int j = r >> 8, k = r & 255;
    float v;
    if (k < 128) v = gcw[i * 16384 + j * 128 + k];
    else         v = biw[i * 16384 + j * 128 + (k - 128)];
    __nv_bfloat16 hi = __float2bfloat16_rn(v);
    __nv_bfloat16 lo = __float2bfloat16_rn(v - __bfloat162float(hi));
    g_wbf_hi[t] = hi;
    g_wbf_lo[t] = lo;
    if (k == 0) g_bias[i * 128 + j] = gcb[i * 128 + j] + bib[i * 128 + j];
}

// ---------------- init ----------------
__global__ void init_kernel(const float* __restrict__ emb, int N) {
    int t = blockIdx.x * blockDim.x + threadIdx.x;
    int total = N * 32;
    if (t >= total) return;
    int n = t / 32, f = t % 32;
    float4 v = ((const float4*)emb)[t];
    ((float4*)g_ego[0])[t] = v;
    ((float4*)g_all)[(size_t)n * 128 + f] = v;
}

// ---------------- CSR build ----------------
__global__ void csr_zero_kernel(int N) {
    for (int i = blockIdx.x * blockDim.x + threadIdx.x; i < N; i += gridDim.x * blockDim.x) {
        g_deg[i] = 0;
        g_cur[i] = 0;
    }
}
__global__ void csr_hist_kernel(const int* __restrict__ ei, int E) {
    for (int e = blockIdx.x * blockDim.x + threadIdx.x; e < E; e += gridDim.x * blockDim.x)
        atomicAdd(&g_deg[ei[e]], 1);
}
__global__ void csr_scan_local_kernel(int N) {
    __shared__ int sm[1024];
    int b = blockIdx.x, t = threadIdx.x;
    int i = b * 1024 + t;
    int v = (i < N) ? g_deg[i] : 0;
    sm[t] = v;
    __syncthreads();
#pragma unroll
    for (int off = 1; off < 1024; off <<= 1) {
        int x = sm[t];
        int y = (t >= off) ? sm[t - off] : 0;
        __syncthreads();
        sm[t] = x + y;
        __syncthreads();
    }
    if (i < N) g_off[i] = sm[t] - v;
    if (t == 1023) g_bsum[b] = sm[t];
}
__global__ void csr_scan_bsum_kernel(int nblk) {
    __shared__ int sm[256];
    int t = threadIdx.x;
    int v = (t < nblk) ? g_bsum[t] : 0;
    sm[t] = v;
    __syncthreads();
#pragma unroll
    for (int off = 1; off < 256; off <<= 1) {
        int x = sm[t];
        int y = (t >= off) ? sm[t - off] : 0;
        __syncthreads();
        sm[t] = x + y;
        __syncthreads();
    }
    g_bsum[t] = sm[t] - v;
}
__global__ void csr_scan_add_kernel(int N, int E) {
    int i = blockIdx.x * blockDim.x + threadIdx.x;
    if (i < N) g_off[i] += g_bsum[i >> 10];
    if (i == 0) g_off[N] = E;
}
__global__ void csr_fill_kernel(const int* __restrict__ ei, const float* __restrict__ wt, int E) {
    for (int e = blockIdx.x * blockDim.x + threadIdx.x; e < E; e += gridDim.x * blockDim.x) {
        int row = ei[e];
        int pos = g_off[row] + atomicAdd(&g_cur[row], 1);
        g_ccol[pos] = ei[E + e];
        g_cw[pos] = wt[e];
    }
}

// ---------------- gather: msg = A@ego, then emit H=[msg|ego*msg] split-bf16 ----------------
__device__ __forceinline__ void split_pair(float x, float y, uint32_t& hi, uint32_t& lo) {
    __nv_bfloat162 h = __floats2bfloat162_rn(x, y);
    __nv_bfloat162 l = __floats2bfloat162_rn(x - __bfloat162float(h.x), y - __bfloat162float(h.y));
    hi = *reinterpret_cast<uint32_t*>(&h);
    lo = *reinterpret_cast<uint32_t*>(&l);
}

__global__ void gather_kernel(int sel, int N) {
    int g = blockIdx.x * blockDim.x + threadIdx.x;
    int n = g >> 5;
    if (n >= N) return;
    int lane = g & 31;
    int s = g_off[n], e = g_off[n + 1];
    const float* __restrict__ ego = g_ego[sel];
    float4 acc = make_float4(0.f, 0.f, 0.f, 0.f);
    int i = s;
    for (; i + 4 <= e; i += 4) {
        int c0 = __ldg(g_ccol + i), c1 = __ldg(g_ccol + i + 1);
        int c2 = __ldg(g_ccol + i + 2), c3 = __ldg(g_ccol + i + 3);
        float w0 = __ldg(g_cw + i), w1 = __ldg(g_cw + i + 1);
        float w2 = __ldg(g_cw + i + 2), w3 = __ldg(g_cw + i + 3);
        float4 v0 = __ldg((const float4*)(ego + (size_t)c0 * DIM) + lane);
        float4 v1 = __ldg((const float4*)(ego + (size_t)c1 * DIM) + lane);
        float4 v2 = __ldg((const float4*)(ego + (size_t)c2 * DIM) + lane);
        float4 v3 = __ldg((const float4*)(ego + (size_t)c3 * DIM) + lane);
        acc.x += w0 * v0.x; acc.y += w0 * v0.y; acc.z += w0 * v0.z; acc.w += w0 * v0.w;
        acc.x += w1 * v1.x; acc.y += w1 * v1.y; acc.z += w1 * v1.z; acc.w += w1 * v1.w;
        acc.x += w2 * v2.x; acc.y += w2 * v2.y; acc.z += w2 * v2.z; acc.w += w2 * v2.w;
        acc.x += w3 * v3.x; acc.y += w3 * v3.y; acc.z += w3 * v3.z; acc.w += w3 * v3.w;
    }
    for (; i < e; i++) {
        int c = __ldg(g_ccol + i);
        float w = __ldg(g_cw + i);
        float4 v = __ldg((const float4*)(ego + (size_t)c * DIM) + lane);
        acc.x += w * v.x; acc.y += w * v.y; acc.z += w * v.z; acc.w += w * v.w;
    }
    // own ego row (coalesced)
    float4 eg = __ldg((const float4*)(ego + (size_t)n * DIM) + lane);
    float4 pr = make_float4(acc.x * eg.x, acc.y * eg.y, acc.z * eg.z, acc.w * eg.w);

    char* hi_row = (char*)(g_h_hi + (size_t)n * 256);
    char* lo_row = (char*)(g_h_lo + (size_t)n * 256);
    uint2 mh, ml, ph, pl;
    split_pair(acc.x, acc.y, mh.x, ml.x);
    split_pair(acc.z, acc.w, mh.y, ml.y);
    split_pair(pr.x, pr.y, ph.x, pl.x);
    split_pair(pr.z, pr.w, ph.y, pl.y);
    *(uint2*)(hi_row + lane * 8) = mh;
    *(uint2*)(lo_row + lane * 8) = ml;
    *(uint2*)(hi_row + 256 + lane * 8) = ph;
    *(uint2*)(lo_row + 256 + lane * 8) = pl;
}

// ================= layer GEMM: pipelined cp.async + mma.sync (bf16x3) =================
// Block 128x128, K=256 in 4 stages of 64. 256 threads, 8 warps, warp tile 64x32.
// SMEM: resident B (4 kb-tiles x 16KB, hi then lo), double-buffered A stages.
#define SMEM_B_HI 0          // 65536
#define SMEM_B_LO 65536      // 65536
#define SMEM_A    131072     // 2 stages x (Ahi 16KB + Alo 16KB)
#define LK_SMEM   196608
#define EPI_ROWPART 69632    // float [128][4]  (reuses B region post-MMA)
#define EPI_SCALE   71680    // float [128]

__device__ __forceinline__ void issue_a_stage(char* smem, int kb, int buf, int n0, int N, int tid) {
    uint32_t abase = smem_u32(smem + SMEM_A + buf * 32768);
    const char* hsrc = (const char*)g_h_hi;
    const char* lsrc = (const char*)g_h_lo;
#pragma unroll
    for (int it = 0; it < 4; it++) {
        int idx = tid + 256 * it;           // 1024 chunks
        int row = idx >> 3, c = idx & 7;
        int n = n0 + row;
        uint32_t sz = (n < N) ? 16u : 0u;
        size_t so = (size_t)(n < N ? n : 0) * 512 + kb * 128 + c * 16;
        uint32_t ci = (uint32_t)(row * 8 + (c ^ (row & 7))) * 16;
        cp_async16(abase + ci, hsrc + so, sz);
        cp_async16(abase + 16384 + ci, lsrc + so, sz);
    }
}

__global__ __launch_bounds__(256, 1) void layer_kernel(int sel, int layer, int N) {
    extern __shared__ char smem[];
    const uint32_t sb = smem_u32(smem);
    const int tid = threadIdx.x;
    const int wid = tid >> 5;
    const int lid = tid & 31;
    const int n0 = blockIdx.x * 128;
    const int wm = wid >> 2;
    const int wn = wid & 3;

    // ---- issue resident B (full layer W, hi+lo, 128KB) + A stage 0 ----
    {
        const char* wh = (const char*)(g_wbf_hi) + (size_t)layer * 65536;
        const char* wl = (const char*)(g_wbf_lo) + (size_t)layer * 65536;
        uint32_t bh = sb + SMEM_B_HI, bl = sb + SMEM_B_LO;
#pragma unroll
        for (int it = 0; it < 16; it++) {
            int idx = tid + 256 * it;       // 4096 chunks: [kb 4][row 128][c 8]
            int kb = idx >> 10;
            int r = (idx >> 3) & 127;
            int c = idx & 7;
            size_t so = (size_t)r * 512 + kb * 128 + c * 16;
            uint32_t ci = (uint32_t)(kb * 16384) + (uint32_t)(r * 8 + (c ^ (r & 7))) * 16;
            cp_async16(bh + ci, wh + so, 16);
            cp_async16(bl + ci, wl + so, 16);
        }
    }
    issue_a_stage(smem, 0, 0, n0, N, tid);
    CP_COMMIT();
    issue_a_stage(smem, 1, 1, n0, N, tid);
    CP_COMMIT();

    float acc[4][4][4];
#pragma unroll
    for (int mt = 0; mt < 4; mt++)
#pragma unroll
        for (int nt = 0; nt < 4; nt++)
#pragma unroll
            for (int c = 0; c < 4; c++) acc[mt][nt][c] = 0.f;

#pragma unroll
    for (int kb = 0; kb < 4; kb++) {
        if (kb < 3) CP_WAIT1(); else CP_WAIT0();
        __syncthreads();

        uint32_t abase = sb + SMEM_A + (kb & 1) * 32768;
        uint32_t bhbase = sb + SMEM_B_HI + kb * 16384;
        uint32_t blbase = sb + SMEM_B_LO + kb * 16384;
#pragma unroll
        for (int ks = 0; ks < 4; ks++) {
            uint32_t ahi[4][4], alo[4][4];
            int lr = lid & 15, lk = lid >> 4;
#pragma unroll
            for (int mt = 0; mt < 4; mt++) {
                int r = wm * 64 + mt * 16 + lr;
                int kc = ks * 2 + lk;
                uint32_t off = (uint32_t)(r * 8 + (kc ^ (r & 7))) * 16;
                LDSM_X4(ahi[mt], abase + off);
                LDSM_X4(alo[mt], abase + 16384 + off);
            }
            uint32_t bhi[2][4], blo[2][4];
            int nr = (lid & 7) + ((lid >> 4) << 3);
            int nk = (lid >> 3) & 1;
#pragma unroll
            for (int np = 0; np < 2; np++) {
                int r = wn * 32 + np * 16 + nr;
                int kc = ks * 2 + nk;
                uint32_t off = (uint32_t)(r * 8 + (kc ^ (r & 7))) * 16;
                LDSM_X4(bhi[np], bhbase + off);
                LDSM_X4(blo[np], blbase + off);
            }
#pragma unroll
            for (int mt = 0; mt < 4; mt++)
#pragma unroll
                for (int nt = 0; nt < 4; nt++) {
                    const uint32_t* bh = &bhi[nt >> 1][(nt & 1) * 2];
                    const uint32_t* bl = &blo[nt >> 1][(nt & 1) * 2];
                    mma16816(acc[mt][nt], ahi[mt], bh);
                    mma16816(acc[mt][nt], ahi[mt], bl);
                    mma16816(acc[mt][nt], alo[mt], bh);
                }
        }
        __syncthreads();
        if (kb + 2 < 4) { issue_a_stage(smem, kb + 2, kb & 1, n0, N, tid); CP_COMMIT(); }
    }

    // ================= epilogue (reuses B SMEM region) =================
    float* stage = (float*)smem;                      // [128][136]
    float* rowpart = (float*)(smem + EPI_ROWPART);    // [128][4]
    const float* bias = g_bias + layer * 128;
    int qid = lid >> 2, qt = lid & 3;
#pragma unroll
    for (int mt = 0; mt < 4; mt++) {
        int rA = wm * 64 + mt * 16 + qid;
        int rB = rA + 8;
        float sqa = 0.f, sqb = 0.f;
#pragma unroll
        for (int nt = 0; nt < 4; nt++) {
            int col = wn * 32 + nt * 8 + 2 * qt;
            float b0 = __ldg(bias + col), b1 = __ldg(bias + col + 1);
            float* c = acc[mt][nt];
            float x0 = c[0] + b0, x1 = c[1] + b1;
            float y0 = c[2] + b0, y1 = c[3] + b1;
            x0 = x0 > 0.f ? x0 : 0.2f * x0;
            x1 = x1 > 0.f ? x1 : 0.2f * x1;
            y0 = y0 > 0.f ? y0 : 0.2f * y0;
            y1 = y1 > 0.f ? y1 : 0.2f * y1;
            stage[rA * 136 + col] = x0;
            stage[rA * 136 + col + 1] = x1;
            stage[rB * 136 + col] = y0;
            stage[rB * 136 + col + 1] = y1;
            sqa += x0 * x0 + x1 * x1;
            sqb += y0 * y0 + y1 * y1;
        }
        sqa += __shfl_xor_sync(0xffffffffu, sqa, 1);
        sqa += __shfl_xor_sync(0xffffffffu, sqa, 2);
        sqb += __shfl_xor_sync(0xffffffffu, sqb, 1);
        sqb += __shfl_xor_sync(0xffffffffu, sqb, 2);
        if (qt == 0) {
            rowpart[rA * 4 + wn] = sqa;
            rowpart[rB * 4 + wn] = sqb;
        }
    }
    __syncthreads();
    float* scl = (float*)(smem + EPI_SCALE);
    if (tid < 128) {
        float tot = rowpart[tid * 4] + rowpart[tid * 4 + 1] + rowpart[tid * 4 + 2] + rowpart[tid * 4 + 3];
        scl[tid] = 1.0f / fmaxf(sqrtf(tot), 1e-12f);
    }
    __syncthreads();
    float* ego_out = g_ego[sel ^ 1];
    int seg = (layer + 1) * 128;
#pragma unroll
    for (int it = 0; it < 16; it++) {
        int idx = tid + 256 * it;
        int r = idx >> 5, j = idx & 31;
        int n = n0 + r;
        if (n < N) {
            float4 v = *(const float4*)(stage + r * 136 + j * 4);
            ((float4*)(ego_out + (size_t)n * DIM))[j] = v;
            float s = scl[r];
            float4 sv = make_float4(v.x * s, v.y * s, v.z * s, v.w * s);
            ((float4*)(g_all + (size_t)n * 512 + seg))[j] = sv;
        }
    }
}

// ---------------- scoring ----------------
__global__ void score_kernel(const int* __restrict__ eli, float* __restrict__ out, int Q) {
    int g = blockIdx.x * blockDim.x + threadIdx.x;
    int q = g >> 5;
    if (q >= Q) return;
    int lane = g & 31;
    int s = __ldg(eli + q);
    int d = __ldg(eli + Q + q);
    const float4* ps = (const float4*)(g_all + (size_t)s * 512);
    const float4* pd = (const float4*)(g_all + (size_t)d * 512);
    float sum = 0.f;
#pragma unroll
    for (int t = 0; t < 4; t++) {
        float4 a = __ldg(ps + lane + 32 * t);
        float4 b = __ldg(pd + lane + 32 * t);
        sum += a.x * b.x + a.y * b.y + a.z * b.z + a.w * b.w;
    }
#pragma unroll
    for (int off = 16; off > 0; off >>= 1)
        sum += __shfl_xor_sync(0xffffffffu, sum, off);
    if (lane == 0) out[q] = sum;
}

// ---------------- launch ----------------
extern "C" void kernel_launch(void* const* d_in, const int* in_sizes, int n_in,
                              void* d_out, int out_size) {
    const int*   ei  = (const int*)d_in[0];
    const int*   eli = (const int*)d_in[1];
    const float* wt  = (const float*)d_in[2];
    const float* emb = (const float*)d_in[3];
    const float* gcw = (const float*)d_in[4];
    const float* gcb = (const float*)d_in[5];
    const float* biw = (const float*)d_in[6];
    const float* bib = (const float*)d_in[7];

    int E = in_sizes[2];
    int Q = in_sizes[1] / 2;
    int N = in_sizes[3] / DIM;

    static bool attr_set = false;
    if (!attr_set) {
        cudaFuncSetAttribute(layer_kernel, cudaFuncAttributeMaxDynamicSharedMemorySize, LK_SMEM);
        attr_set = true;
    }

    prep_kernel<<<(3 * 128 * 256 + 255) / 256, 256>>>(gcw, gcb, biw, bib);
    init_kernel<<<(N * 32 + 255) / 256, 256>>>(emb, N);

    int nblk = (N + 1023) / 1024;
    csr_zero_kernel<<<256, 256>>>(N);
    csr_hist_kernel<<<1024, 256>>>(ei, E);
    csr_scan_local_kernel<<<nblk, 1024>>>(N);
    csr_scan_bsum_kernel<<<1, 256>>>(nblk);
    csr_scan_add_kernel<<<(N + 255) / 256, 256>>>(N, E);
    csr_fill_kernel<<<1024, 256>>>(ei, wt, E);

    int sel = 0;
    for (int i = 0; i < 3; i++) {
        long long gthreads = (long long)N * 32;
        int gblocks = (int)((gthreads + 255) / 256);
        gather_kernel<<<gblocks, 256>>>(sel, N);
        layer_kernel<<<(N + 127) / 128, 256, LK_SMEM>>>(sel, i, N);
        sel ^= 1;
    }
    score_kernel<<<(Q * 32 + 255) / 256, 256>>>(eli, (float*)d_out, Q);
}